// round 6
// baseline (speedup 1.0000x reference)
#include <cuda_runtime.h>

// ---------------------------------------------------------------------------
// SNN: 5 LIF layers, 25 steps, B=2048.
//   cur_i = relu(h @ W_i^T + b_i);  reset = (mem_old>1);  mem' = 0.95*mem + cur - reset
//   spk = (mem' > 1);  outputs: spk5 record then tanh(mem5) record, each [25,2048,784]
// Layer-1 current is time-invariant -> whole layer-1 recurrence precomputed
// for all 25 steps before the time loop (no intra-loop dependence).
// FROZEN (Round 3 source, re-audited twice) — no bench data yet; holding the
// audited design stable so the first successful bench yields a clean baseline.
// ---------------------------------------------------------------------------

#define BATCH 2048
#define T_STEPS 25
#define D0 100
#define D1 128
#define D2 256
#define D3 512
#define D4 1024
#define D5 784

#define OFF_M2 0
#define OFF_M3 (OFF_M2 + BATCH * D2)
#define OFF_M4 (OFF_M3 + BATCH * D3)
#define OFF_M5 (OFF_M4 + BATCH * D4)
#define MEM_TOTAL (OFF_M5 + BATCH * D5)

#define OFF_S2 0
#define OFF_S3 (OFF_S2 + BATCH * D2)
#define OFF_S4 (OFF_S3 + BATCH * D3)
#define SPK_TOTAL (OFF_S4 + BATCH * D4)

__device__ float g_mem[MEM_TOTAL];             // layers 2..5 membrane state
__device__ float g_spk[SPK_TOTAL];             // layers 2..4 spikes (current step)
__device__ float g_cur1[BATCH * D1];           // constant layer-1 current
__device__ float g_spk1[T_STEPS * BATCH * D1]; // precomputed layer-1 spikes, all steps

// fast tanh via exp identity; output-only (no feedback into recurrence)
__device__ __forceinline__ float fast_tanh(float x) {
    float e = __expf(2.0f * x);
    return 1.0f - 2.0f / (e + 1.0f);
}

// unfused LIF update (separate rn mul/add/sub, mimicking XLA elementwise HLOs)
__device__ __forceinline__ void lif_update(float mo, float cur, float& mn, float& sp) {
    float reset = (mo > 1.0f) ? 1.0f : 0.0f;
    mn = __fsub_rn(__fadd_rn(__fmul_rn(0.95f, mo), cur), reset);
    sp = (mn > 1.0f) ? 1.0f : 0.0f;
}

__global__ void zero_kernel(float* __restrict__ p, int n) {
    int i = blockIdx.x * blockDim.x + threadIdx.x;
    if (i < n) p[i] = 0.0f;
}

// Full 25-step layer-1 recurrence per element (cur is constant in t).
__global__ void lif1_all_kernel(const float* __restrict__ cur,
                                float* __restrict__ spk_all) {
    int i = blockIdx.x * blockDim.x + threadIdx.x;  // grid sized exactly: BATCH*D1
    float c = cur[i];
    float m = 0.0f;
#pragma unroll
    for (int t = 0; t < T_STEPS; t++) {
        float mn, sp;
        lif_update(m, c, mn, sp);
        m = mn;
        spk_all[(size_t)t * (BATCH * D1) + i] = sp;
    }
}

// ---------------------------------------------------------------------------
// gemm_lif (128x128 tile): C[M,N] = A[M,K] @ W[N,K]^T (+bias, relu), LIF epi.
// 256 threads, 8x8 microtile, TK=8, double-buffered SMEM.
// mode 0: write relu(cur) to spk    (constant layer-1 current)
// mode 1: LIF update -> mem, spk
// mode 2: LIF + tanh(mem') -> tout  (layer 5)
// M % 128 == 0 assumed; N,K arbitrary (guarded); N % 4 == 0 for stores.
// ---------------------------------------------------------------------------
__global__ void __launch_bounds__(256, 2) gemm_lif(
    const float* __restrict__ A, const float* __restrict__ W,
    const float* __restrict__ bias, float* __restrict__ mem,
    float* __restrict__ spk, float* __restrict__ tout,
    int N, int K, int mode)
{
    __shared__ float As[2][8][128];
    __shared__ float Bs[2][8][128];

    const int tid = threadIdx.x;
    const int m0 = blockIdx.y * 128;
    const int n0 = blockIdx.x * 128;
    const int lr = tid >> 1;          // 0..127 : row within tile (load)
    const int lc = (tid & 1) * 4;     // 0 or 4 : k-offset (load)
    const int tx = tid & 15;          // 0..15 : col group (compute)
    const int ty = tid >> 4;          // 0..15 : row group (compute)

    float acc[8][8];
#pragma unroll
    for (int i = 0; i < 8; i++)
#pragma unroll
        for (int j = 0; j < 8; j++) acc[i][j] = 0.0f;

    const float* arow = A + (size_t)(m0 + lr) * K;
    const int nrow = n0 + lr;
    const bool bvalid = (nrow < N);
    const float* brow = W + (size_t)(bvalid ? nrow : 0) * K;

    const int nk = (K + 7) >> 3;

    float4 av, bv;

    // prologue: k-tile 0 -> buffer 0
    {
        int k = lc;
        if (k + 3 < K) {
            av = *(const float4*)(arow + k);
            bv = bvalid ? *(const float4*)(brow + k) : make_float4(0.f, 0.f, 0.f, 0.f);
        } else {
            float a_[4], b_[4];
#pragma unroll
            for (int j = 0; j < 4; j++) {
                int kk = k + j;
                a_[j] = (kk < K) ? arow[kk] : 0.0f;
                b_[j] = (kk < K && bvalid) ? brow[kk] : 0.0f;
            }
            av = make_float4(a_[0], a_[1], a_[2], a_[3]);
            bv = make_float4(b_[0], b_[1], b_[2], b_[3]);
        }
        As[0][lc + 0][lr] = av.x; As[0][lc + 1][lr] = av.y;
        As[0][lc + 2][lr] = av.z; As[0][lc + 3][lr] = av.w;
        Bs[0][lc + 0][lr] = bv.x; Bs[0][lc + 1][lr] = bv.y;
        Bs[0][lc + 2][lr] = bv.z; Bs[0][lc + 3][lr] = bv.w;
    }
    __syncthreads();

    for (int kt = 0; kt < nk; kt++) {
        const int buf = kt & 1;
        const bool more = (kt + 1) < nk;
        if (more) {
            int k = (kt + 1) * 8 + lc;
            if (k + 3 < K) {
                av = *(const float4*)(arow + k);
                bv = bvalid ? *(const float4*)(brow + k) : make_float4(0.f, 0.f, 0.f, 0.f);
            } else {
                float a_[4], b_[4];
#pragma unroll
                for (int j = 0; j < 4; j++) {
                    int kk = k + j;
                    a_[j] = (kk < K) ? arow[kk] : 0.0f;
                    b_[j] = (kk < K && bvalid) ? brow[kk] : 0.0f;
                }
                av = make_float4(a_[0], a_[1], a_[2], a_[3]);
                bv = make_float4(b_[0], b_[1], b_[2], b_[3]);
            }
        }
#pragma unroll
        for (int kk = 0; kk < 8; kk++) {
            float4 a0 = *(const float4*)&As[buf][kk][ty * 4];
            float4 a1 = *(const float4*)&As[buf][kk][64 + ty * 4];
            float4 b0 = *(const float4*)&Bs[buf][kk][tx * 4];
            float4 b1 = *(const float4*)&Bs[buf][kk][64 + tx * 4];
            float ar[8] = {a0.x, a0.y, a0.z, a0.w, a1.x, a1.y, a1.z, a1.w};
            float br[8] = {b0.x, b0.y, b0.z, b0.w, b1.x, b1.y, b1.z, b1.w};
#pragma unroll
            for (int i = 0; i < 8; i++)
#pragma unroll
                for (int j = 0; j < 8; j++)
                    acc[i][j] = fmaf(ar[i], br[j], acc[i][j]);
        }
        if (more) {
            const int nb = buf ^ 1;
            As[nb][lc + 0][lr] = av.x; As[nb][lc + 1][lr] = av.y;
            As[nb][lc + 2][lr] = av.z; As[nb][lc + 3][lr] = av.w;
            Bs[nb][lc + 0][lr] = bv.x; Bs[nb][lc + 1][lr] = bv.y;
            Bs[nb][lc + 2][lr] = bv.z; Bs[nb][lc + 3][lr] = bv.w;
        }
        __syncthreads();
    }

    // epilogue: bias + relu + LIF  (bias loads hoisted: same 2 float4 per thread)
    const int col0 = n0 + tx * 4;
    const int col1 = n0 + 64 + tx * 4;
    const bool v0 = (col0 < N);
    const bool v1 = (col1 < N);
    float4 bia0 = v0 ? *(const float4*)(bias + col0) : make_float4(0.f, 0.f, 0.f, 0.f);
    float4 bia1 = v1 ? *(const float4*)(bias + col1) : make_float4(0.f, 0.f, 0.f, 0.f);

#pragma unroll
    for (int i = 0; i < 8; i++) {
        const int row = m0 + ((i & 4) << 4) + ty * 4 + (i & 3);
#pragma unroll
        for (int jb = 0; jb < 2; jb++) {
            const int col = jb ? col1 : col0;
            if (jb ? !v1 : !v0) continue;
            const float4 bi = jb ? bia1 : bia0;
            const size_t off = (size_t)row * N + col;
            float c0 = fmaxf(__fadd_rn(acc[i][jb * 4 + 0], bi.x), 0.0f);
            float c1 = fmaxf(__fadd_rn(acc[i][jb * 4 + 1], bi.y), 0.0f);
            float c2 = fmaxf(__fadd_rn(acc[i][jb * 4 + 2], bi.z), 0.0f);
            float c3 = fmaxf(__fadd_rn(acc[i][jb * 4 + 3], bi.w), 0.0f);
            if (mode == 0) {
                *(float4*)(spk + off) = make_float4(c0, c1, c2, c3);
            } else {
                float4 mo = *(const float4*)(mem + off);
                float4 mn, sp;
                lif_update(mo.x, c0, mn.x, sp.x);
                lif_update(mo.y, c1, mn.y, sp.y);
                lif_update(mo.z, c2, mn.z, sp.z);
                lif_update(mo.w, c3, mn.w, sp.w);
                *(float4*)(mem + off) = mn;
                *(float4*)(spk + off) = sp;
                if (mode == 2) {
                    *(float4*)(tout + off) = make_float4(
                        fast_tanh(mn.x), fast_tanh(mn.y),
                        fast_tanh(mn.z), fast_tanh(mn.w));
                }
            }
        }
    }
}

// ---------------------------------------------------------------------------
// gemm64_lif (64x64 tile): for small-N layers (L2: N=256, L3: N=512) where the
// 128x128 grid underfills the 148 SMs. 256 threads, 4x4 microtile, TK=16,
// double-buffered. Requires K % 16 == 0, N % 64 == 0, M % 64 == 0.
// LIF update -> mem, spk.
// ---------------------------------------------------------------------------
__global__ void __launch_bounds__(256, 2) gemm64_lif(
    const float* __restrict__ A, const float* __restrict__ W,
    const float* __restrict__ bias, float* __restrict__ mem,
    float* __restrict__ spk, int N, int K)
{
    __shared__ float As[2][16][64];
    __shared__ float Bs[2][16][64];

    const int tid = threadIdx.x;
    const int m0 = blockIdx.y * 64;
    const int n0 = blockIdx.x * 64;
    const int lr = tid >> 2;          // 0..63 : row within tile (load)
    const int lc = (tid & 3) * 4;     // 0,4,8,12 : k-offset (load)
    const int tx = tid & 15;          // 0..15 : col group
    const int ty = tid >> 4;          // 0..15 : row group

    float acc[4][4];
#pragma unroll
    for (int i = 0; i < 4; i++)
#pragma unroll
        for (int j = 0; j < 4; j++) acc[i][j] = 0.0f;

    const float* arow = A + (size_t)(m0 + lr) * K;
    const float* brow = W + (size_t)(n0 + lr) * K;
    const int nk = K >> 4;

    float4 av, bv;

    // prologue
    av = *(const float4*)(arow + lc);
    bv = *(const float4*)(brow + lc);
    As[0][lc + 0][lr] = av.x; As[0][lc + 1][lr] = av.y;
    As[0][lc + 2][lr] = av.z; As[0][lc + 3][lr] = av.w;
    Bs[0][lc + 0][lr] = bv.x; Bs[0][lc + 1][lr] = bv.y;
    Bs[0][lc + 2][lr] = bv.z; Bs[0][lc + 3][lr] = bv.w;
    __syncthreads();

    for (int kt = 0; kt < nk; kt++) {
        const int buf = kt & 1;
        const bool more = (kt + 1) < nk;
        if (more) {
            int k = (kt + 1) * 16 + lc;
            av = *(const float4*)(arow + k);
            bv = *(const float4*)(brow + k);
        }
#pragma unroll
        for (int kk = 0; kk < 16; kk++) {
            float4 a0 = *(const float4*)&As[buf][kk][ty * 4];
            float4 b0 = *(const float4*)&Bs[buf][kk][tx * 4];
            float ar[4] = {a0.x, a0.y, a0.z, a0.w};
            float br[4] = {b0.x, b0.y, b0.z, b0.w};
#pragma unroll
            for (int i = 0; i < 4; i++)
#pragma unroll
                for (int j = 0; j < 4; j++)
                    acc[i][j] = fmaf(ar[i], br[j], acc[i][j]);
        }
        if (more) {
            const int nb = buf ^ 1;
            As[nb][lc + 0][lr] = av.x; As[nb][lc + 1][lr] = av.y;
            As[nb][lc + 2][lr] = av.z; As[nb][lc + 3][lr] = av.w;
            Bs[nb][lc + 0][lr] = bv.x; Bs[nb][lc + 1][lr] = bv.y;
            Bs[nb][lc + 2][lr] = bv.z; Bs[nb][lc + 3][lr] = bv.w;
        }
        __syncthreads();
    }

    // epilogue: bias + relu + LIF
    const int col = n0 + tx * 4;
    const float4 bi = *(const float4*)(bias + col);
#pragma unroll
    for (int i = 0; i < 4; i++) {
        const int row = m0 + ty * 4 + i;
        const size_t off = (size_t)row * N + col;
        float c0 = fmaxf(__fadd_rn(acc[i][0], bi.x), 0.0f);
        float c1 = fmaxf(__fadd_rn(acc[i][1], bi.y), 0.0f);
        float c2 = fmaxf(__fadd_rn(acc[i][2], bi.z), 0.0f);
        float c3 = fmaxf(__fadd_rn(acc[i][3], bi.w), 0.0f);
        float4 mo = *(const float4*)(mem + off);
        float4 mn, sp;
        lif_update(mo.x, c0, mn.x, sp.x);
        lif_update(mo.y, c1, mn.y, sp.y);
        lif_update(mo.z, c2, mn.z, sp.z);
        lif_update(mo.w, c3, mn.w, sp.w);
        *(float4*)(mem + off) = mn;
        *(float4*)(spk + off) = sp;
    }
}

extern "C" void kernel_launch(void* const* d_in, const int* in_sizes, int n_in,
                              void* d_out, int out_size) {
    const float* x  = (const float*)d_in[0];
    const float* W1 = (const float*)d_in[1];
    const float* b1 = (const float*)d_in[2];
    const float* W2 = (const float*)d_in[3];
    const float* b2 = (const float*)d_in[4];
    const float* W3 = (const float*)d_in[5];
    const float* b3 = (const float*)d_in[6];
    const float* W4 = (const float*)d_in[7];
    const float* b4 = (const float*)d_in[8];
    const float* W5 = (const float*)d_in[9];
    const float* b5 = (const float*)d_in[10];
    float* out = (float*)d_out;

    float *memp, *spkp, *cur1p, *spk1p;
    cudaGetSymbolAddress((void**)&memp, g_mem);
    cudaGetSymbolAddress((void**)&spkp, g_spk);
    cudaGetSymbolAddress((void**)&cur1p, g_cur1);
    cudaGetSymbolAddress((void**)&spk1p, g_spk1);

    // deterministic state reset every call (layers 2..5)
    zero_kernel<<<(MEM_TOTAL + 255) / 256, 256>>>(memp, MEM_TOTAL);

    // time-invariant layer-1 current: relu(x @ W1^T + b1)
    gemm_lif<<<dim3(1, BATCH / 128), 256>>>(x, W1, b1, nullptr, cur1p, nullptr,
                                            D1, D0, 0);
    // full layer-1 recurrence for all 25 steps (independent of other layers)
    lif1_all_kernel<<<(BATCH * D1) / 256, 256>>>(cur1p, spk1p);

    const size_t SZ = (size_t)BATCH * D5;
    for (int t = 0; t < T_STEPS; t++) {
        gemm64_lif<<<dim3(D2 / 64, BATCH / 64), 256>>>(
            spk1p + (size_t)t * (BATCH * D1), W2, b2,
            memp + OFF_M2, spkp + OFF_S2, D2, D1);
        gemm64_lif<<<dim3(D3 / 64, BATCH / 64), 256>>>(
            spkp + OFF_S2, W3, b3, memp + OFF_M3, spkp + OFF_S3, D3, D2);
        gemm_lif<<<dim3(D4 / 128, BATCH / 128), 256>>>(
            spkp + OFF_S3, W4, b4, memp + OFF_M4, spkp + OFF_S4, nullptr, D4, D3, 1);
        gemm_lif<<<dim3((D5 + 127) / 128, BATCH / 128), 256>>>(
            spkp + OFF_S4, W5, b5, memp + OFF_M5,
            out + (size_t)t * SZ, out + (size_t)(T_STEPS + t) * SZ, D5, D4, 2);
    }
}